// round 3
// baseline (speedup 1.0000x reference)
#include <cuda_runtime.h>

#define Sdim 512
#define SS (Sdim * Sdim)
#define Bn 8
#define KT 64
#define NTHREADS 256

// Sheared copy of x: Dall[i][b][j] = x[b][j][i-j] for j <= i (rest untouched).
__device__ float Dall[Sdim][Bn][Sdim];   // 8.4 MB static scratch

// Pass-through copy for positions with r + c >= S.
__global__ void copy_tail_kernel(const float* __restrict__ x,
                                 float* __restrict__ out) {
    int idx = blockIdx.x * blockDim.x + threadIdx.x;
    if (idx >= Bn * SS) return;
    int rc = idx & (SS - 1);
    int r = rc >> 9;
    int c = rc & (Sdim - 1);
    if (r + c >= Sdim) out[idx] = x[idx];
}

// Shear transpose: Dall[i][b][j] = x[b][j][i-j]. 32x32 smem tiles, both
// global access streams fully coalesced.
__global__ void __launch_bounds__(1024)
shear_kernel(const float* __restrict__ x) {
    const int b  = blockIdx.z;
    const int i0 = blockIdx.y * 32;
    const int j0 = blockIdx.x * 32;
    if (i0 + 31 < j0) return;            // tile entirely in invalid j > i region

    __shared__ float tile[32][33];
    const int tx = threadIdx.x;
    const int ty = threadIdx.y;

    // tile[ty][tx] = x[b][j0+ty][c], c = i0-j0+tx-ty (row-contiguous read)
    const int c = i0 - j0 + tx - ty;
    float v = 0.0f;
    if (c >= 0 && c < Sdim)
        v = x[((size_t)b * Sdim + (j0 + ty)) * Sdim + c];
    tile[ty][tx] = v;
    __syncthreads();

    // Dall[i0+ty][b][j0+tx] = x[b][j0+tx][(i0+ty)-(j0+tx)] = tile[tx][ty]
    const int i = i0 + ty;
    const int j = j0 + tx;
    if (j <= i)
        Dall[i][b][j] = tile[tx][ty];    // row-contiguous write
}

// One CTA per (diagonal i, 64-wide k tile).
//   out[b, i-k, k] = sum_j W[i,k,j] * D[b][j] + bias[i,k]
__global__ void __launch_bounds__(NTHREADS)
diag_linear_kernel(const float* __restrict__ W,
                   const float* __restrict__ bias,
                   float* __restrict__ out) {
    const int i = Sdim - 1 - (int)blockIdx.y;   // heavy diagonals first
    const int k0 = (int)blockIdx.x * KT;
    if (k0 > i) return;

    const int len = i + 1;
    const int kend = min(k0 + KT, len);

    __shared__ float Ds[Bn][Sdim];

    const int tid = threadIdx.x;

    // Coalesced copy of the pre-sheared diagonal (L2-resident Dall).
    {
        const int n4 = (len + 3) >> 2;           // float4s per batch row
        const float4* src = (const float4*)&Dall[i][0][0];
        float4* dst = (float4*)&Ds[0][0];
        #pragma unroll
        for (int b = 0; b < Bn; b++) {
            for (int t = tid; t < n4; t += NTHREADS)
                dst[b * (Sdim / 4) + t] = src[b * (Sdim / 4) + t];
        }
    }
    __syncthreads();

    const int warp = tid >> 5;
    const int lane = tid & 31;
    const float* Wbase = W + (size_t)i * Sdim * Sdim;

    if (k0 + KT <= len) {
        // Full tile: warp handles 4 k-rows; double-buffered W prefetch.
        #pragma unroll
        for (int p = 0; p < 2; p++) {
            const int kk = k0 + p * 32 + warp * 4;
            const float4* wr0 = (const float4*)(Wbase + (size_t)(kk + 0) * Sdim);
            const float4* wr1 = (const float4*)(Wbase + (size_t)(kk + 1) * Sdim);
            const float4* wr2 = (const float4*)(Wbase + (size_t)(kk + 2) * Sdim);
            const float4* wr3 = (const float4*)(Wbase + (size_t)(kk + 3) * Sdim);

            float acc[4][Bn];
            #pragma unroll
            for (int u = 0; u < 4; u++)
                #pragma unroll
                for (int b = 0; b < Bn; b++) acc[u][b] = 0.0f;

            const int len4 = len >> 2;
            float4 w0, w1, w2, w3;
            int t = lane;
            if (t < len4) {
                w0 = __ldcs(wr0 + t); w1 = __ldcs(wr1 + t);
                w2 = __ldcs(wr2 + t); w3 = __ldcs(wr3 + t);
            }
            while (t < len4) {
                const int tn = t + 32;
                float4 n0, n1, n2, n3;
                if (tn < len4) {
                    n0 = __ldcs(wr0 + tn); n1 = __ldcs(wr1 + tn);
                    n2 = __ldcs(wr2 + tn); n3 = __ldcs(wr3 + tn);
                }
                #pragma unroll
                for (int b = 0; b < Bn; b++) {
                    float4 d = ((const float4*)Ds[b])[t];
                    acc[0][b] += w0.x * d.x + w0.y * d.y + w0.z * d.z + w0.w * d.w;
                    acc[1][b] += w1.x * d.x + w1.y * d.y + w1.z * d.z + w1.w * d.w;
                    acc[2][b] += w2.x * d.x + w2.y * d.y + w2.z * d.z + w2.w * d.w;
                    acc[3][b] += w3.x * d.x + w3.y * d.y + w3.z * d.z + w3.w * d.w;
                }
                t = tn;
                w0 = n0; w1 = n1; w2 = n2; w3 = n3;
            }
            // Remainder (len % 4)
            const int rem = len & 3;
            if (lane < rem) {
                const int j = (len4 << 2) + lane;
                float w0s = Wbase[(size_t)(kk + 0) * Sdim + j];
                float w1s = Wbase[(size_t)(kk + 1) * Sdim + j];
                float w2s = Wbase[(size_t)(kk + 2) * Sdim + j];
                float w3s = Wbase[(size_t)(kk + 3) * Sdim + j];
                #pragma unroll
                for (int b = 0; b < Bn; b++) {
                    float dv = Ds[b][j];
                    acc[0][b] += w0s * dv;
                    acc[1][b] += w1s * dv;
                    acc[2][b] += w2s * dv;
                    acc[3][b] += w3s * dv;
                }
            }

            #pragma unroll
            for (int off = 16; off > 0; off >>= 1) {
                #pragma unroll
                for (int u = 0; u < 4; u++)
                    #pragma unroll
                    for (int b = 0; b < Bn; b++)
                        acc[u][b] += __shfl_xor_sync(0xffffffffu, acc[u][b], off);
            }

            if (lane == 0) {
                #pragma unroll
                for (int u = 0; u < 4; u++) {
                    const int k = kk + u;
                    const float bb = __ldg(bias + (size_t)i * Sdim + k);
                    const int r = i - k;
                    #pragma unroll
                    for (int b = 0; b < Bn; b++) {
                        out[(size_t)b * SS + (size_t)r * Sdim + k] = acc[u][b] + bb;
                    }
                }
            }
        }
    } else {
        // Boundary path (partial k tile): warp-per-k, stride 8.
        for (int k = k0 + warp; k < kend; k += (NTHREADS / 32)) {
            const float* wrow = Wbase + (size_t)k * Sdim;
            const float4* w4p = (const float4*)wrow;

            float acc[Bn];
            #pragma unroll
            for (int b = 0; b < Bn; b++) acc[b] = 0.0f;

            const int len4 = len >> 2;
            for (int t = lane; t < len4; t += 32) {
                float4 w4 = __ldcs(w4p + t);
                #pragma unroll
                for (int b = 0; b < Bn; b++) {
                    float4 d = ((const float4*)Ds[b])[t];
                    acc[b] += w4.x * d.x + w4.y * d.y + w4.z * d.z + w4.w * d.w;
                }
            }
            for (int j = (len4 << 2) + lane; j < len; j += 32) {
                float w = wrow[j];
                #pragma unroll
                for (int b = 0; b < Bn; b++) acc[b] += w * Ds[b][j];
            }

            #pragma unroll
            for (int off = 16; off > 0; off >>= 1) {
                #pragma unroll
                for (int b = 0; b < Bn; b++)
                    acc[b] += __shfl_xor_sync(0xffffffffu, acc[b], off);
            }

            if (lane == 0) {
                const float bb = __ldg(bias + (size_t)i * Sdim + k);
                const int r = i - k;
                #pragma unroll
                for (int b = 0; b < Bn; b++) {
                    out[(size_t)b * SS + (size_t)r * Sdim + k] = acc[b] + bb;
                }
            }
        }
    }
}

extern "C" void kernel_launch(void* const* d_in, const int* in_sizes, int n_in,
                              void* d_out, int out_size) {
    const float* x = (const float*)d_in[0];
    const float* W = (const float*)d_in[1];
    const float* b = (const float*)d_in[2];
    float* out = (float*)d_out;

    copy_tail_kernel<<<(Bn * SS + NTHREADS - 1) / NTHREADS, NTHREADS>>>(x, out);

    dim3 sgrid(Sdim / 32, Sdim / 32, Bn);
    shear_kernel<<<sgrid, dim3(32, 32)>>>(x);

    dim3 grid(Sdim / KT, Sdim);
    diag_linear_kernel<<<grid, NTHREADS>>>(W, b, out);
}

// round 4
// speedup vs baseline: 1.3418x; 1.3418x over previous
#include <cuda_runtime.h>

#define Sdim 512
#define SS (Sdim * Sdim)
#define Bn 8
#define KT 32
#define NTHREADS 128

// Sheared copy of x: Dall[i][b][j] = x[b][j][i-j] for j <= i.
__device__ float Dall[Sdim][Bn][Sdim];   // 8.4 MB static scratch

// Pass-through copy, vectorized per row: out[b][r][c] = x[b][r][c] for c >= S-r.
// One block per (r, b); the segment is contiguous and coalesced.
__global__ void __launch_bounds__(128)
copy_tail_kernel(const float* __restrict__ x, float* __restrict__ out) {
    const int r = blockIdx.x;           // 0..511 ; segment length = r
    const int b = blockIdx.y;
    const int c0 = Sdim - r;
    const float* src = x + ((size_t)b * Sdim + r) * Sdim;
    float* dst = out + ((size_t)b * Sdim + r) * Sdim;
    for (int c = c0 + threadIdx.x; c < Sdim; c += 128)
        dst[c] = src[c];
}

// Shear transpose: Dall[i][b][j] = x[b][j][i-j]. 32x32 smem tiles; both
// global streams coalesced.
__global__ void __launch_bounds__(1024)
shear_kernel(const float* __restrict__ x) {
    const int b  = blockIdx.z;
    const int i0 = blockIdx.y * 32;
    const int j0 = blockIdx.x * 32;
    if (i0 + 31 < j0) return;

    __shared__ float tile[32][33];
    const int tx = threadIdx.x;
    const int ty = threadIdx.y;

    const int c = i0 - j0 + tx - ty;
    float v = 0.0f;
    if (c >= 0 && c < Sdim)
        v = x[((size_t)b * Sdim + (j0 + ty)) * Sdim + c];
    tile[ty][tx] = v;
    __syncthreads();

    const int i = i0 + ty;
    const int j = j0 + tx;
    if (j <= i)
        Dall[i][b][j] = tile[tx][ty];
}

// One CTA per (diagonal i, 32-wide k tile), 128 threads (4 warps).
//   out[b, i-k, k] = sum_j W[i,k,j] * D[b][j] + bias[i,k]
__global__ void __launch_bounds__(NTHREADS)
diag_linear_kernel(const float* __restrict__ W,
                   const float* __restrict__ bias,
                   float* __restrict__ out) {
    const int i = Sdim - 1 - (int)blockIdx.y;   // heavy diagonals first
    const int k0 = (int)blockIdx.x * KT;
    if (k0 > i) return;

    const int len = i + 1;
    const int kend = min(k0 + KT, len);

    __shared__ float Ds[Bn][Sdim];

    const int tid = threadIdx.x;

    // Coalesced copy of the pre-sheared diagonal (L2-resident Dall).
    {
        const int n4 = (len + 3) >> 2;
        const float4* src = (const float4*)&Dall[i][0][0];
        float4* dst = (float4*)&Ds[0][0];
        #pragma unroll
        for (int b = 0; b < Bn; b++) {
            for (int t = tid; t < n4; t += NTHREADS)
                dst[b * (Sdim / 4) + t] = src[b * (Sdim / 4) + t];
        }
    }
    __syncthreads();

    const int warp = tid >> 5;
    const int lane = tid & 31;
    const float* Wbase = W + (size_t)i * Sdim * Sdim;

    if (k0 + KT <= len) {
        // Full tile: each warp handles 4 k-rows per pass, 2 passes.
        #pragma unroll
        for (int p = 0; p < 2; p++) {
            const int kk = k0 + p * 16 + warp * 4;
            const float4* wr0 = (const float4*)(Wbase + (size_t)(kk + 0) * Sdim);
            const float4* wr1 = (const float4*)(Wbase + (size_t)(kk + 1) * Sdim);
            const float4* wr2 = (const float4*)(Wbase + (size_t)(kk + 2) * Sdim);
            const float4* wr3 = (const float4*)(Wbase + (size_t)(kk + 3) * Sdim);

            float acc[4][Bn];
            #pragma unroll
            for (int u = 0; u < 4; u++)
                #pragma unroll
                for (int b = 0; b < Bn; b++) acc[u][b] = 0.0f;

            const int len4 = len >> 2;
            for (int t = lane; t < len4; t += 32) {
                float4 w0 = __ldcs(wr0 + t);
                float4 w1 = __ldcs(wr1 + t);
                float4 w2 = __ldcs(wr2 + t);
                float4 w3 = __ldcs(wr3 + t);
                #pragma unroll
                for (int b = 0; b < Bn; b++) {
                    float4 d = ((const float4*)Ds[b])[t];
                    acc[0][b] += w0.x * d.x + w0.y * d.y + w0.z * d.z + w0.w * d.w;
                    acc[1][b] += w1.x * d.x + w1.y * d.y + w1.z * d.z + w1.w * d.w;
                    acc[2][b] += w2.x * d.x + w2.y * d.y + w2.z * d.z + w2.w * d.w;
                    acc[3][b] += w3.x * d.x + w3.y * d.y + w3.z * d.z + w3.w * d.w;
                }
            }
            // Remainder (len % 4)
            const int rem = len & 3;
            if (lane < rem) {
                const int j = (len4 << 2) + lane;
                float w0s = Wbase[(size_t)(kk + 0) * Sdim + j];
                float w1s = Wbase[(size_t)(kk + 1) * Sdim + j];
                float w2s = Wbase[(size_t)(kk + 2) * Sdim + j];
                float w3s = Wbase[(size_t)(kk + 3) * Sdim + j];
                #pragma unroll
                for (int b = 0; b < Bn; b++) {
                    float dv = Ds[b][j];
                    acc[0][b] += w0s * dv;
                    acc[1][b] += w1s * dv;
                    acc[2][b] += w2s * dv;
                    acc[3][b] += w3s * dv;
                }
            }

            #pragma unroll
            for (int off = 16; off > 0; off >>= 1) {
                #pragma unroll
                for (int u = 0; u < 4; u++)
                    #pragma unroll
                    for (int b = 0; b < Bn; b++)
                        acc[u][b] += __shfl_xor_sync(0xffffffffu, acc[u][b], off);
            }

            if (lane == 0) {
                #pragma unroll
                for (int u = 0; u < 4; u++) {
                    const int k = kk + u;
                    const float bb = __ldg(bias + (size_t)i * Sdim + k);
                    const int r = i - k;
                    #pragma unroll
                    for (int b = 0; b < Bn; b++) {
                        out[(size_t)b * SS + (size_t)r * Sdim + k] = acc[u][b] + bb;
                    }
                }
            }
        }
    } else {
        // Boundary path (partial k tile): warp-per-k, stride 4.
        for (int k = k0 + warp; k < kend; k += (NTHREADS / 32)) {
            const float* wrow = Wbase + (size_t)k * Sdim;
            const float4* w4p = (const float4*)wrow;

            float acc[Bn];
            #pragma unroll
            for (int b = 0; b < Bn; b++) acc[b] = 0.0f;

            const int len4 = len >> 2;
            for (int t = lane; t < len4; t += 32) {
                float4 w4 = __ldcs(w4p + t);
                #pragma unroll
                for (int b = 0; b < Bn; b++) {
                    float4 d = ((const float4*)Ds[b])[t];
                    acc[b] += w4.x * d.x + w4.y * d.y + w4.z * d.z + w4.w * d.w;
                }
            }
            for (int j = (len4 << 2) + lane; j < len; j += 32) {
                float w = wrow[j];
                #pragma unroll
                for (int b = 0; b < Bn; b++) acc[b] += w * Ds[b][j];
            }

            #pragma unroll
            for (int off = 16; off > 0; off >>= 1) {
                #pragma unroll
                for (int b = 0; b < Bn; b++)
                    acc[b] += __shfl_xor_sync(0xffffffffu, acc[b], off);
            }

            if (lane == 0) {
                const float bb = __ldg(bias + (size_t)i * Sdim + k);
                const int r = i - k;
                #pragma unroll
                for (int b = 0; b < Bn; b++) {
                    out[(size_t)b * SS + (size_t)r * Sdim + k] = acc[b] + bb;
                }
            }
        }
    }
}

extern "C" void kernel_launch(void* const* d_in, const int* in_sizes, int n_in,
                              void* d_out, int out_size) {
    const float* x = (const float*)d_in[0];
    const float* W = (const float*)d_in[1];
    const float* b = (const float*)d_in[2];
    float* out = (float*)d_out;

    dim3 tgrid(Sdim, Bn);
    copy_tail_kernel<<<tgrid, 128>>>(x, out);

    dim3 sgrid(Sdim / 32, Sdim / 32, Bn);
    shear_kernel<<<sgrid, dim3(32, 32)>>>(x);

    dim3 grid(Sdim / KT, Sdim);
    diag_linear_kernel<<<grid, NTHREADS>>>(W, b, out);
}